// round 4
// baseline (speedup 1.0000x reference)
#include <cuda_runtime.h>
#include <cstdint>

// Problem constants (fixed by the dataset)
#define Tn 2000
#define Bn 64
#define Vn 163
#define Ln 200
#define Sn 401          // 2*L+1 extended states
#define NEGF (-1e30f)
#define NS 16           // cp.async prefetch depth (power of 2)
#define NTH 416         // 13 warps; thread s owns extended state s (s < 401)
#define KMIN (-(1 << 29))

// Scratch (no cudaMalloc allowed)
__device__ float g_lse[Tn * Bn];     // log-sum-exp per (t,b)
__device__ float g_partial[Bn];      // per-utterance -(log pe); finalize adds +sum(lse)

// ---------------------------------------------------------------------------
// Kernel 1: per-row log-sum-exp over vocab. One warp per (t,b) row.
// ---------------------------------------------------------------------------
__global__ void lse_kernel(const float* __restrict__ logits) {
    int warp = (blockIdx.x * blockDim.x + threadIdx.x) >> 5;
    if (warp >= Tn * Bn) return;
    int lane = threadIdx.x & 31;
    const float* p = logits + (size_t)warp * Vn;

    float v[6];
    float m = NEGF;
#pragma unroll
    for (int k = 0; k < 6; k++) {
        int i = lane + 32 * k;
        v[k] = (i < Vn) ? p[i] : NEGF;
        m = fmaxf(m, v[k]);
    }
#pragma unroll
    for (int o = 16; o; o >>= 1) m = fmaxf(m, __shfl_xor_sync(0xffffffffu, m, o));

    float sum = 0.f;
#pragma unroll
    for (int k = 0; k < 6; k++) sum += __expf(v[k] - m);
#pragma unroll
    for (int o = 16; o; o >>= 1) sum += __shfl_xor_sync(0xffffffffu, sum, o);

    if (lane == 0) g_lse[warp] = m + __logf(sum);
}

// term aligned to kmax: keep (d==0), downshift one unit (d==-1), else negligible
__device__ __forceinline__ float termf(float m, int d) {
    return (d == 0) ? m : ((d == -1) ? m * 0x1p-64f : 0.f);
}

// ---------------------------------------------------------------------------
// Kernel 2: CTC alpha recursion in EXTENDED-EXPONENT linear domain.
// One CTA per batch element; thread s owns state s. Each alpha is
// (mantissa, k): value = m * 2^(64k), m kept in [2^-32, 2^32).
// p_new[s] = (p[s] + p[s-1] + allow*p[s-2]) * exp(logit[e]); softmax norm
// factored out (added back in finalize). No MUFU on the serial chain.
// Single barrier per step; logits prefetched NS deep via cp.async.
// Row t's copy is cp.async group t+1 -> wait_group NS-2 guarantees it.
// ---------------------------------------------------------------------------
__global__ __launch_bounds__(NTH, 1) void ctc_alpha_kernel(
    const float* __restrict__ logits,
    const int*   __restrict__ labels,
    const int*   __restrict__ act_lens,
    const int*   __restrict__ label_lens)
{
    __shared__ float  ring[NS][164];      // u = exp(logit) per step (163 used)
    __shared__ float2 pk[2][Sn + 8];      // {mantissa, bit-cast exponent}

    const int b   = blockIdx.x;
    const int tid = threadIdx.x;
    const int act = act_lens[b];
    const int lab = label_lens[b];
    const int s   = tid;
    const bool isState = (s < Sn);

    bool validS = false;
    bool allow  = false;   // alpha[s-2] path allowed
    int  e = 0;            // vocab index for state s (0 = blank)
    int  i2 = 0;
    if (isState) {
        validS = s < 2 * lab + 1;
        if (s & 1) {
            e = labels[b * Ln + ((s - 1) >> 1)];
            if (s >= 3) allow = (e != labels[b * Ln + ((s - 3) >> 1)]);
        }
        i2 = (s >= 2) ? s - 2 : 0;
    }

    const float* base = logits + (size_t)b * Vn;   // (t,b,v) at base + t*B*V + v

    // prologue: prefetch rows 0..NS-1 (row d -> group d)
#pragma unroll
    for (int d = 0; d < NS; d++) {
        if (tid < Vn) {
            uint32_t sa = (uint32_t)__cvta_generic_to_shared(&ring[d][tid]);
            asm volatile("cp.async.ca.shared.global [%0], [%1], 4;"
                         :: "r"(sa), "l"(base + (size_t)d * Bn * Vn + tid));
        }
        asm volatile("cp.async.commit_group;");
    }

    float a0m = 0.f;   // own state, register copy
    int   a0k = 0;

    for (int t = 0; t < act; t++) {
        const int slot = t & (NS - 1);
        asm volatile("cp.async.wait_group %0;" :: "n"(NS - 2));
        if (tid < Vn) ring[slot][tid] = __expf(ring[slot][tid]);
        __syncthreads();   // u visible; step t-1's reads of overwritten buffers done

        // prefetch row (t-1)+NS into the slot freed at step t-1
        if (t >= 1) {
            int tl = t - 1 + NS; if (tl > Tn - 1) tl = Tn - 1;
            const int ps = (t - 1) & (NS - 1);
            if (tid < Vn) {
                uint32_t sa = (uint32_t)__cvta_generic_to_shared(&ring[ps][tid]);
                asm volatile("cp.async.ca.shared.global [%0], [%1], 4;"
                             :: "r"(sa), "l"(base + (size_t)tl * Bn * Vn + tid));
            }
        }
        asm volatile("cp.async.commit_group;");

        if (isState) {
            float newm; int newk;
            if (t == 0) {
                newm = (s < 2) ? ring[slot][e] : 0.f;
                newk = 0;
            } else {
                const float2* P = pk[(t + 1) & 1];
                float2 n1 = (s >= 1) ? P[s - 1] : make_float2(0.f, 0.f);
                float2 n2 = P[i2];
                float m1 = n1.x, m2 = n2.x;
                int k1 = __float_as_int(n1.y), k2 = __float_as_int(n2.y);

                int kk0 = (a0m > 0.f) ? a0k : KMIN;
                int kk1 = (s >= 1 && m1 > 0.f) ? k1 : KMIN;
                int kk2 = (allow && m2 > 0.f) ? k2 : KMIN;
                int km  = max(kk0, max(kk1, kk2));

                if (km == KMIN) {
                    newm = 0.f; newk = 0;
                } else {
                    float acc = termf(a0m, kk0 - km)
                              + termf(m1,  kk1 - km)
                              + termf(m2,  kk2 - km);
                    newm = acc * ring[slot][e];
                    newk = km;
                    if (newm >= 0x1p32f)      { newm *= 0x1p-64f; newk++; }
                    else if (newm < 0x1p-32f) { if (newm > 0.f) { newm *= 0x1p64f; newk--; } }
                }
                if (!validS) newm = 0.f;
            }
            pk[t & 1][s] = make_float2(newm, __int_as_float(newk));
            a0m = newm; a0k = newk;
        }
    }

    asm volatile("cp.async.wait_group 0;");
    __syncthreads();

    if (tid == 0) {
        const float2* A = pk[(act - 1) & 1];
        int end = 2 * lab;                        // lab >= 100
        float2 ve = A[end], vp = A[end - 1];
        int ke = (ve.x > 0.f) ? __float_as_int(ve.y) : KMIN;
        int kp = (vp.x > 0.f) ? __float_as_int(vp.y) : KMIN;
        int km = max(ke, kp);
        float pe = termf(ve.x, ke - km) + termf(vp.x, kp - km);
        double ll;
        if (km == KMIN || pe <= 0.f) ll = -1e30;  // unreachable in practice
        else ll = log((double)pe) + (double)km * (64.0 * 0.6931471805599453);
        g_partial[b] = (float)(-ll);              // finalize adds +sum(lse)
    }
}

// ---------------------------------------------------------------------------
// Kernel 3: per-b sum of lse over t < act, combine with partial, then
// total = sum(loss) / sum(act_lens). One block, 1024 threads.
// ---------------------------------------------------------------------------
__global__ __launch_bounds__(1024, 1) void finalize_kernel(
    const int* __restrict__ act_lens, float* __restrict__ out)
{
    __shared__ float part[16][64];
    __shared__ double red_l[2], red_a[2];

    const int bb = threadIdx.x & 63;     // batch index
    const int y  = threadIdx.x >> 6;     // 0..15
    const int act = act_lens[bb];

    float sacc = 0.f;
    for (int t = y; t < Tn; t += 16) {
        float v = g_lse[t * Bn + bb];    // coalesced across bb
        sacc += (t < act) ? v : 0.f;
    }
    part[y][bb] = sacc;
    __syncthreads();

    double loss = 0.0, aln = 0.0;
    if (threadIdx.x < 64) {
        float tot = 0.f;
#pragma unroll
        for (int k = 0; k < 16; k++) tot += part[k][bb];
        loss = (double)g_partial[bb] + (double)tot;
        aln  = (double)act;
#pragma unroll
        for (int o = 16; o; o >>= 1) {
            loss += __shfl_xor_sync(0xffffffffu, loss, o);
            aln  += __shfl_xor_sync(0xffffffffu, aln,  o);
        }
        if ((threadIdx.x & 31) == 0) {
            red_l[threadIdx.x >> 5] = loss;
            red_a[threadIdx.x >> 5] = aln;
        }
    }
    __syncthreads();
    if (threadIdx.x == 0)
        out[0] = (float)((red_l[0] + red_l[1]) / (red_a[0] + red_a[1]));
}

// ---------------------------------------------------------------------------
extern "C" void kernel_launch(void* const* d_in, const int* in_sizes, int n_in,
                              void* d_out, int out_size)
{
    const float* logits     = (const float*)d_in[0];  // [T, B, V]
    const int*   labels     = (const int*)d_in[1];    // [B, L]
    const int*   act_lens   = (const int*)d_in[2];    // [B]
    const int*   label_lens = (const int*)d_in[3];    // [B]

    lse_kernel<<<(Tn * Bn + 7) / 8, 256>>>(logits);
    ctc_alpha_kernel<<<Bn, NTH>>>(logits, labels, act_lens, label_lens);
    finalize_kernel<<<1, 1024>>>(act_lens, (float*)d_out);
}

// round 5
// speedup vs baseline: 1.6018x; 1.6018x over previous
#include <cuda_runtime.h>
#include <cstdint>

// Problem constants (fixed by the dataset)
#define Tn 2000
#define Bn 64
#define Vn 163
#define Vp 164          // padded u row; element [163] == 0.0f (zero sentinel)
#define Ln 200
#define Sn 401          // 2*L+1 extended states
#define NEGF (-1e30f)
#define CHK 13          // states per lane (32*13 = 416 >= 401)
#define KMIN (-(1 << 29))

// Scratch (device globals; no cudaMalloc allowed)
__device__ float g_u[Tn * Bn * Vp];   // exp(logits), 0-padded  (~84 MB)
__device__ float g_lse[Tn * Bn];      // log-sum-exp per (t,b)
__device__ float g_partial[Bn];       // per-utterance -(log pe); finalize adds +sum(lse)

// ---------------------------------------------------------------------------
// Kernel 1: u = exp(logits) (+ zero pad) and lse per row. One warp per row.
// ---------------------------------------------------------------------------
__global__ void prep_kernel(const float* __restrict__ logits) {
    int row = (blockIdx.x * blockDim.x + threadIdx.x) >> 5;
    if (row >= Tn * Bn) return;
    int lane = threadIdx.x & 31;
    const float* p = logits + (size_t)row * Vn;
    float* up = g_u + (size_t)row * Vp;

    float v[6];
    float m = NEGF;
#pragma unroll
    for (int k = 0; k < 6; k++) {
        int i = lane + 32 * k;
        v[k] = (i < Vn) ? p[i] : NEGF;
        m = fmaxf(m, v[k]);
    }
    // write exp(logit); i==163 gets exp(NEGF)==0 -> the zero sentinel
#pragma unroll
    for (int k = 0; k < 6; k++) {
        int i = lane + 32 * k;
        if (i < Vp) up[i] = __expf(v[k]);
    }
#pragma unroll
    for (int o = 16; o; o >>= 1) m = fmaxf(m, __shfl_xor_sync(0xffffffffu, m, o));
    float sum = 0.f;
#pragma unroll
    for (int k = 0; k < 6; k++) sum += __expf(v[k] - m);
#pragma unroll
    for (int o = 16; o; o >>= 1) sum += __shfl_xor_sync(0xffffffffu, sum, o);
    if (lane == 0) g_lse[row] = m + __logf(sum);
}

// term aligned to kmax: keep (d==0), downshift one 64-bit unit (d==-1), else 0
__device__ __forceinline__ float termf(float m, int d) {
    return (d == 0) ? m : ((d == -1) ? m * 0x1p-64f : 0.f);
}

// ---------------------------------------------------------------------------
// Kernel 2: CTC alpha, ONE WARP PER BATCH ELEMENT, register-resident.
// Lane owns states [lane*13, lane*13+12]; value = m * 2^(64*k_lane).
// Neighbor handoff: 3 shuffles/step. Gathers u[t][b][e_j] via LDG with a
// depth-4 register ring (addresses static per thread). No barriers, no MUFU.
// ---------------------------------------------------------------------------
#define BODY(T_, P_) do {                                                       \
    float nm1 = __shfl_up_sync(0xffffffffu, m[CHK-1], 1);                       \
    float nm2 = __shfl_up_sync(0xffffffffu, m[CHK-2], 1);                       \
    int   nk  = __shfl_up_sync(0xffffffffu, kk, 1);                             \
    if (tid == 0) { nm1 = 0.f; nm2 = 0.f; nk = kk; }                            \
    int d = nk - kk;                                                            \
    if (__any_sync(0xffffffffu, d > 0)) {                                       \
        if (d > 0) {  /* neighbor at larger scale: adopt it */                  \
            float dn = (d == 1) ? 0x1p-64f : 0.f;                               \
            _Pragma("unroll") for (int j = 0; j < CHK; j++) m[j] *= dn;         \
            kk = nk; d = 0;                                                     \
        }                                                                       \
    }                                                                           \
    float sc = (d == 0) ? 1.f : ((d == -1) ? 0x1p-64f : 0.f);                   \
    nm1 *= sc; nm2 *= sc;                                                       \
    float nv[CHK];                                                              \
    nv[0] = (m[0] + fmaf(al[0], nm2, nm1)) * buf[P_][0];                        \
    nv[1] = (m[1] + fmaf(al[1], nm1, m[0])) * buf[P_][1];                       \
    _Pragma("unroll") for (int j = 2; j < CHK; j++)                             \
        nv[j] = (m[j] + fmaf(al[j], m[j-2], m[j-1])) * buf[P_][j];              \
    _Pragma("unroll") for (int j = 0; j < CHK; j++) m[j] = nv[j];               \
    int tp = (T_) + 4; if (tp > Tn - 1) tp = Tn - 1;                            \
    const float* rr = ub + (size_t)tp * (Bn * Vp);                              \
    _Pragma("unroll") for (int j = 0; j < CHK; j++) buf[P_][j] = __ldg(rr + e[j]); \
    if (((T_) & 3) == 3) {  /* per-chunk renorm, window [2^-32, 2^32) */        \
        float mx = m[0];                                                        \
        _Pragma("unroll") for (int j = 1; j < CHK; j++) mx = fmaxf(mx, m[j]);   \
        if (mx >= 0x1p32f) {                                                    \
            _Pragma("unroll") for (int j = 0; j < CHK; j++) m[j] *= 0x1p-64f;   \
            kk += 1;                                                            \
        } else if (mx < 0x1p-32f && mx > 0.f) {                                 \
            _Pragma("unroll") for (int j = 0; j < CHK; j++) m[j] *= 0x1p64f;    \
            kk -= 1;                                                            \
        }                                                                       \
    }                                                                           \
} while (0)

__global__ __launch_bounds__(32, 1) void ctc_alpha_kernel(
    const int* __restrict__ labels,
    const int* __restrict__ act_lens,
    const int* __restrict__ label_lens)
{
    const int b   = blockIdx.x;
    const int tid = threadIdx.x;
    const int act = act_lens[b];
    const int lab = label_lens[b];
    const int smax = 2 * lab;          // final blank state

    // static per-state tables (registers)
    int   e[CHK];
    float al[CHK];
#pragma unroll
    for (int j = 0; j < CHK; j++) {
        int s = tid * CHK + j;
        int ee = Vn;                   // zero sentinel (invalid / out of range)
        float af = 0.f;
        if (s < Sn && s <= smax) {
            if (s & 1) {
                ee = labels[b * Ln + ((s - 1) >> 1)];
                if (s >= 3 && ee != labels[b * Ln + ((s - 3) >> 1)]) af = 1.f;
            } else ee = 0;             // blank
        }
        e[j] = ee; al[j] = af;
    }

    const float* ub = g_u + b * Vp;    // (t,b,v) at ub + t*Bn*Vp + v

    // t = 0 init
    float m[CHK];
    int   kk = 0;
#pragma unroll
    for (int j = 0; j < CHK; j++) m[j] = 0.f;
    if (tid == 0) { m[0] = ub[e[0]]; m[1] = ub[e[1]]; }   // states 0,1

    // prefetch rows t = 1..4 (act >= 1000 always)
    float buf[4][CHK];
#pragma unroll
    for (int p = 0; p < 4; p++) {
        const float* r = ub + (size_t)(1 + p) * (Bn * Vp);
#pragma unroll
        for (int j = 0; j < CHK; j++) buf[p][j] = __ldg(r + e[j]);
    }

    int t = 1;
    for (; t + 3 < act; t += 4) {
        BODY(t, 0); BODY(t + 1, 1); BODY(t + 2, 2); BODY(t + 3, 3);
    }
    if (t < act) { BODY(t, 0); t++; }
    if (t < act) { BODY(t, 1); t++; }
    if (t < act) { BODY(t, 2); }

    // publish final alphas and combine
    __shared__ float2 fin[32 * CHK];
#pragma unroll
    for (int j = 0; j < CHK; j++)
        fin[tid * CHK + j] = make_float2(m[j], __int_as_float(kk));
    __syncwarp();

    if (tid == 0) {
        float2 ve = fin[smax], vp2 = fin[smax - 1];
        int ke = (ve.x  > 0.f) ? __float_as_int(ve.y)  : KMIN;
        int kp = (vp2.x > 0.f) ? __float_as_int(vp2.y) : KMIN;
        int km = max(ke, kp);
        float pe = termf(ve.x, ke - km) + termf(vp2.x, kp - km);
        double ll;
        if (km == KMIN || pe <= 0.f) ll = -1e30;   // unreachable in practice
        else ll = log((double)pe) + (double)km * (64.0 * 0.6931471805599453);
        g_partial[b] = (float)(-ll);               // finalize adds +sum(lse)
    }
}

// ---------------------------------------------------------------------------
// Kernel 3: per-b sum of lse over t < act, combine, total = sum/frames.
// ---------------------------------------------------------------------------
__global__ __launch_bounds__(1024, 1) void finalize_kernel(
    const int* __restrict__ act_lens, float* __restrict__ out)
{
    __shared__ float part[16][64];
    __shared__ double red_l[2], red_a[2];

    const int bb = threadIdx.x & 63;
    const int y  = threadIdx.x >> 6;
    const int act = act_lens[bb];

    float sacc = 0.f;
    for (int t = y; t < Tn; t += 16) {
        float v = g_lse[t * Bn + bb];
        sacc += (t < act) ? v : 0.f;
    }
    part[y][bb] = sacc;
    __syncthreads();

    if (threadIdx.x < 64) {
        float tot = 0.f;
#pragma unroll
        for (int k = 0; k < 16; k++) tot += part[k][bb];
        double loss = (double)g_partial[bb] + (double)tot;
        double aln  = (double)act;
#pragma unroll
        for (int o = 16; o; o >>= 1) {
            loss += __shfl_xor_sync(0xffffffffu, loss, o);
            aln  += __shfl_xor_sync(0xffffffffu, aln,  o);
        }
        if ((threadIdx.x & 31) == 0) {
            red_l[threadIdx.x >> 5] = loss;
            red_a[threadIdx.x >> 5] = aln;
        }
    }
    __syncthreads();
    if (threadIdx.x == 0)
        out[0] = (float)((red_l[0] + red_l[1]) / (red_a[0] + red_a[1]));
}

// ---------------------------------------------------------------------------
extern "C" void kernel_launch(void* const* d_in, const int* in_sizes, int n_in,
                              void* d_out, int out_size)
{
    const float* logits     = (const float*)d_in[0];  // [T, B, V]
    const int*   labels     = (const int*)d_in[1];    // [B, L]
    const int*   act_lens   = (const int*)d_in[2];    // [B]
    const int*   label_lens = (const int*)d_in[3];    // [B]

    prep_kernel<<<(Tn * Bn + 7) / 8, 256>>>(logits);
    ctc_alpha_kernel<<<Bn, 32>>>(labels, act_lens, label_lens);
    finalize_kernel<<<1, 1024>>>(act_lens, (float*)d_out);
}

// round 6
// speedup vs baseline: 2.5235x; 1.5754x over previous
#include <cuda_runtime.h>
#include <cstdint>

// Problem constants (fixed by the dataset)
#define Tn 2000
#define Bn 64
#define Vn 163
#define Vp 164          // padded u row; element [163] == 0.0f (zero sentinel)
#define Ln 200
#define Sn 401          // 2*L+1 extended states
#define NEGF (-1e30f)
#define CHK 14          // states per lane (even => j parity == state parity)
#define NOD 7           // odd (label) states per lane
#define DP  8           // prefetch depth (steps)
#define RS  (Bn * Vp)   // row stride in floats
#define KMIN (-(1 << 29))

// Scratch (device globals; no cudaMalloc allowed)
__device__ float g_u[Tn * Bn * Vp];   // exp(logits), 0-padded  (~84 MB)
__device__ float g_lse[Tn * Bn];      // log-sum-exp per (t,b)
__device__ float g_partial[Bn];       // per-utterance -(log pe); finalize adds +sum(lse)

// ---------------------------------------------------------------------------
// Kernel 1: u = exp(logits) (+ zero pad) and lse per row. One warp per row.
// ---------------------------------------------------------------------------
__global__ void prep_kernel(const float* __restrict__ logits) {
    int row = (blockIdx.x * blockDim.x + threadIdx.x) >> 5;
    if (row >= Tn * Bn) return;
    int lane = threadIdx.x & 31;
    const float* p = logits + (size_t)row * Vn;
    float* up = g_u + (size_t)row * Vp;

    float v[6];
    float m = NEGF;
#pragma unroll
    for (int k = 0; k < 6; k++) {
        int i = lane + 32 * k;
        v[k] = (i < Vn) ? p[i] : NEGF;
        m = fmaxf(m, v[k]);
    }
#pragma unroll
    for (int k = 0; k < 6; k++) {
        int i = lane + 32 * k;
        if (i < Vp) up[i] = __expf(v[k]);   // i==163 -> exp(NEGF)==0 sentinel
    }
#pragma unroll
    for (int o = 16; o; o >>= 1) m = fmaxf(m, __shfl_xor_sync(0xffffffffu, m, o));
    float sum = 0.f;
#pragma unroll
    for (int k = 0; k < 6; k++) sum += __expf(v[k] - m);
#pragma unroll
    for (int o = 16; o; o >>= 1) sum += __shfl_xor_sync(0xffffffffu, sum, o);
    if (lane == 0) g_lse[row] = m + __logf(sum);
}

// term aligned to kmax: keep (d==0), downshift one 64-bit unit (d==-1), else 0
__device__ __forceinline__ float termf(float m, int d) {
    return (d == 0) ? m : ((d == -1) ? m * 0x1p-64f : 0.f);
}

// ---------------------------------------------------------------------------
// Kernel 2: CTC alpha, one warp per batch element, register-resident.
// Lane owns states [lane*14, lane*14+13]; value = m[j] * 2^(64*kk_lane).
// Even j = blanks (shared u_blank, no skip); odd j = labels (gather, skip fma).
// Exponent sync/adopt/renorm only at 4-step group boundaries (predicated).
// 1 shuffle per step; 8 gathers per step; prefetch 8 steps deep.
// ---------------------------------------------------------------------------
#define PREAMBLE() do {                                                        \
    int nk = __shfl_up_sync(0xffffffffu, kk, 1);                               \
    if (lane == 0) nk = kk;                                                    \
    int d = nk - kk;                                                           \
    float fo = (d <= 0) ? 1.f : ((d == 1) ? 0x1p-64f : 0.f);                   \
    _Pragma("unroll") for (int j = 0; j < CHK; j++) m[j] *= fo;                \
    kk = (d > 0) ? nk : kk;                                                    \
    int dd = (d < 0) ? d : 0;                                                  \
    sc = (dd == 0) ? 1.f : ((dd == -1) ? 0x1p-64f : 0.f);                      \
} while (0)

#define RENORM() do {                                                          \
    float mx = m[0];                                                           \
    _Pragma("unroll") for (int j = 1; j < CHK; j++) mx = fmaxf(mx, m[j]);      \
    float f = 1.f; int dk = 0;                                                 \
    if (mx >= 0x1p32f)                       { f = 0x1p-64f; dk = 1; }         \
    else if (mx < 0x1p-32f && mx > 0.f)      { f = 0x1p64f;  dk = -1; }        \
    _Pragma("unroll") for (int j = 0; j < CHK; j++) m[j] *= f;                 \
    kk += dk;                                                                  \
} while (0)

#define BODY(T_, Q_) do {                                                      \
    float nm = __shfl_up_sync(0xffffffffu, m[CHK - 1], 1);                     \
    if (lane == 0) nm = 0.f;                                                   \
    nm *= sc;                                                                  \
    float ubv = blk[Q_];                                                       \
    float nv[CHK];                                                             \
    nv[0] = (m[0] + nm) * ubv;                                                 \
    nv[1] = (m[1] + fmaf(al[0], nm, m[0])) * ob[Q_][0];                        \
    _Pragma("unroll") for (int i = 1; i < NOD; i++) {                          \
        nv[2*i]   = (m[2*i] + m[2*i - 1]) * ubv;                               \
        nv[2*i+1] = (m[2*i+1] + fmaf(al[i], m[2*i - 1], m[2*i])) * ob[Q_][i];  \
    }                                                                          \
    _Pragma("unroll") for (int j = 0; j < CHK; j++) m[j] = nv[j];              \
    int tp = (T_) + DP; if (tp > Tn - 1) tp = Tn - 1;                          \
    const float* rowp = ubp + (size_t)tp * RS;                                 \
    blk[Q_] = __ldg(rowp);                                                     \
    _Pragma("unroll") for (int i = 0; i < NOD; i++)                            \
        ob[Q_][i] = __ldg(rowp + eo[i]);                                       \
} while (0)

__global__ __launch_bounds__(32, 1) void ctc_alpha_kernel(
    const int* __restrict__ labels,
    const int* __restrict__ act_lens,
    const int* __restrict__ label_lens)
{
    const int b    = blockIdx.x;
    const int lane = threadIdx.x;
    const int act  = act_lens[b];
    const int lab  = label_lens[b];
    const int smax = 2 * lab;            // final blank state (lab >= 100)

    // static per-lane tables: odd states only (even = blanks, implicit)
    int   eo[NOD];
    float al[NOD];
#pragma unroll
    for (int i = 0; i < NOD; i++) {
        int s  = lane * CHK + 2 * i + 1;
        int li = NOD * lane + i;         // (s-1)/2
        int ee = Vn; float af = 0.f;     // sentinel -> u == 0 -> state stays dead
        if (s < Sn && s <= smax) {
            ee = labels[b * Ln + li];
            if (s >= 3) af = (ee != labels[b * Ln + li - 1]) ? 1.f : 0.f;
        }
        eo[i] = ee; al[i] = af;
    }

    const float* ubp = g_u + b * Vp;     // (t,b,v) at ubp + t*RS + v

    float m[CHK];
#pragma unroll
    for (int j = 0; j < CHK; j++) m[j] = 0.f;
    if (lane == 0) { m[0] = __ldg(ubp); m[1] = __ldg(ubp + eo[0]); }  // t=0: s=0,1
    int   kk = 0;
    float sc = 1.f;

    // prologue: slot q holds row t0+q with t0 = 1
    float blk[DP], ob[DP][NOD];
#pragma unroll
    for (int q = 0; q < DP; q++) {
        const float* rowp = ubp + (size_t)(1 + q) * RS;
        blk[q] = __ldg(rowp);
#pragma unroll
        for (int i = 0; i < NOD; i++) ob[q][i] = __ldg(rowp + eo[i]);
    }

    int t0 = 1;
    for (; t0 + 7 < act; t0 += 8) {      // act >= 1000 always
        PREAMBLE();
        BODY(t0 + 0, 0); BODY(t0 + 1, 1); BODY(t0 + 2, 2); BODY(t0 + 3, 3);
        RENORM();
        PREAMBLE();
        BODY(t0 + 4, 4); BODY(t0 + 5, 5); BODY(t0 + 6, 6); BODY(t0 + 7, 7);
        RENORM();
    }
    // tail: <= 7 steps, full handling each step (slot index static per q)
#pragma unroll
    for (int q = 0; q < 7; q++) {
        if (t0 + q < act) { PREAMBLE(); BODY(t0 + q, q); RENORM(); }
    }

    // publish final alphas and combine
    __shared__ float2 fin[32 * CHK];
#pragma unroll
    for (int j = 0; j < CHK; j++)
        fin[lane * CHK + j] = make_float2(m[j], __int_as_float(kk));
    __syncwarp();

    if (lane == 0) {
        float2 ve = fin[smax], vp2 = fin[smax - 1];
        int ke = (ve.x  > 0.f) ? __float_as_int(ve.y)  : KMIN;
        int kp = (vp2.x > 0.f) ? __float_as_int(vp2.y) : KMIN;
        int km = max(ke, kp);
        float pe = termf(ve.x, ke - km) + termf(vp2.x, kp - km);
        double ll;
        if (km == KMIN || pe <= 0.f) ll = -1e30;   // unreachable in practice
        else ll = log((double)pe) + (double)km * (64.0 * 0.6931471805599453);
        g_partial[b] = (float)(-ll);               // finalize adds +sum(lse)
    }
}

// ---------------------------------------------------------------------------
// Kernel 3: per-b sum of lse over t < act, combine, total = sum/frames.
// ---------------------------------------------------------------------------
__global__ __launch_bounds__(1024, 1) void finalize_kernel(
    const int* __restrict__ act_lens, float* __restrict__ out)
{
    __shared__ float part[16][64];
    __shared__ double red_l[2], red_a[2];

    const int bb = threadIdx.x & 63;
    const int y  = threadIdx.x >> 6;
    const int act = act_lens[bb];

    float sacc = 0.f;
    for (int t = y; t < Tn; t += 16) {
        float v = g_lse[t * Bn + bb];
        sacc += (t < act) ? v : 0.f;
    }
    part[y][bb] = sacc;
    __syncthreads();

    if (threadIdx.x < 64) {
        float tot = 0.f;
#pragma unroll
        for (int k = 0; k < 16; k++) tot += part[k][bb];
        double loss = (double)g_partial[bb] + (double)tot;
        double aln  = (double)act;
#pragma unroll
        for (int o = 16; o; o >>= 1) {
            loss += __shfl_xor_sync(0xffffffffu, loss, o);
            aln  += __shfl_xor_sync(0xffffffffu, aln,  o);
        }
        if ((threadIdx.x & 31) == 0) {
            red_l[threadIdx.x >> 5] = loss;
            red_a[threadIdx.x >> 5] = aln;
        }
    }
    __syncthreads();
    if (threadIdx.x == 0)
        out[0] = (float)((red_l[0] + red_l[1]) / (red_a[0] + red_a[1]));
}

// ---------------------------------------------------------------------------
extern "C" void kernel_launch(void* const* d_in, const int* in_sizes, int n_in,
                              void* d_out, int out_size)
{
    const float* logits     = (const float*)d_in[0];  // [T, B, V]
    const int*   labels     = (const int*)d_in[1];    // [B, L]
    const int*   act_lens   = (const int*)d_in[2];    // [B]
    const int*   label_lens = (const int*)d_in[3];    // [B]

    prep_kernel<<<(Tn * Bn + 7) / 8, 256>>>(logits);
    ctc_alpha_kernel<<<Bn, 32>>>(labels, act_lens, label_lens);
    finalize_kernel<<<1, 1024>>>(act_lens, (float*)d_out);
}